// round 3
// baseline (speedup 1.0000x reference)
#include <cuda_runtime.h>
#include <math.h>

#define T_FRAMES 1001
#define BATCH    16
#define LSIG     240000
#define HOP      240
#define DIN      301
#define HID      128
#define GATES    512
#define DOUTN    64
#define NROWS    (T_FRAMES*BATCH)   // 16016

// ------------------------- static device scratch -------------------------
__device__ float2 g_tw[1024];                  // FFT twiddles e^{-2pi i k/2048}
__device__ float  g_feat[NROWS * DIN];         // features [row=t*16+b][301]
__device__ float  g_wihT[DIN * 1024];          // transposed input weights [k][g] (fwd 0..511, bwd 512..1023)
__device__ float  g_bias[1024];
__device__ float  g_pre[NROWS * 1024];         // pre-activations [row][1024]
__device__ float4 g_whh4[2 * 32 * 512];        // [d][k4][g] -> w_hh_d[g][4k4..4k4+3]
__device__ float  g_hcat[NROWS * 256];         // [row][fwd 0..127 | bwd 128..255]
__device__ float  g_owT[256 * 64];             // out_w transposed [k][o]

// ------------------------------ prep kernel ------------------------------
__global__ void prep_kernel(const float* __restrict__ wihf, const float* __restrict__ whhf,
                            const float* __restrict__ bf,   const float* __restrict__ wihb,
                            const float* __restrict__ whhb, const float* __restrict__ bb,
                            const float* __restrict__ outw)
{
    int tid = blockIdx.x * blockDim.x + threadIdx.x;
    int nth = gridDim.x * blockDim.x;

    for (int k = tid; k < 1024; k += nth) {
        float s, c;
        sincospif((float)k * (1.0f/1024.0f), &s, &c);
        g_tw[k] = make_float2(c, -s);
    }
    for (int i = tid; i < DIN*1024; i += nth) {
        int g = i & 1023, k = i >> 10;
        g_wihT[i] = (g < 512) ? wihf[g*DIN + k] : wihb[(g-512)*DIN + k];
    }
    for (int g = tid; g < 1024; g += nth)
        g_bias[g] = (g < 512) ? bf[g] : bb[g-512];
    for (int i = tid; i < 2*32*512; i += nth) {
        int d = i >> 14, r = i & 16383;
        int g = r & 511, k4 = r >> 9;
        const float* W = d ? whhb : whhf;
        const float* p = W + g*HID + 4*k4;
        g_whh4[i] = make_float4(p[0], p[1], p[2], p[3]);
    }
    for (int i = tid; i < 256*64; i += nth) {
        int o = i & 63, k = i >> 6;
        g_owT[i] = outw[o*256 + k];
    }
}

// ---------------------- STFT + harmonic feature kernel --------------------
__global__ __launch_bounds__(256) void stft_kernel(const float* __restrict__ x,
                                                   const float* __restrict__ f0)
{
    __shared__ float2 S[2048];
    int t = blockIdx.x, b = blockIdx.y, tid = threadIdx.x;
    const float* xb = x + b * LSIG;

    // load frame with reflect pad + Hann window (zero-padded to 2048), bit-reversed
    for (int j = tid; j < 2048; j += 256) {
        int q = t*HOP + j - 1024;
        if (q < 0) q = -q;
        else if (q >= LSIG) q = 2*LSIG - 2 - q;
        float v = xb[q];
        int jw = j - 544;
        float wv = (jw >= 0 && jw < 960) ? (0.5f - 0.5f*cospif((float)jw * (1.0f/480.0f))) : 0.0f;
        int rev = __brev((unsigned)j) >> 21;
        S[rev] = make_float2(v*wv, 0.0f);
    }
    __syncthreads();

    // iterative radix-2 DIT
    #pragma unroll
    for (int s = 1; s <= 11; s++) {
        int half = 1 << (s-1);
        int tshift = 11 - s;
        for (int idx = tid; idx < 1024; idx += 256) {
            int pos = idx & (half - 1);
            int grp = idx >> (s-1);
            int i0 = (grp << s) + pos;
            int i1 = i0 + half;
            float2 tw = g_tw[pos << tshift];
            float2 u = S[i0], v = S[i1];
            float tr = tw.x*v.x - tw.y*v.y;
            float ti = tw.x*v.y + tw.y*v.x;
            S[i0] = make_float2(u.x + tr, u.y + ti);
            S[i1] = make_float2(u.x - tr, u.y - ti);
        }
        __syncthreads();
    }

    // harmonic-bin gather -> feature row
    float f0v = f0[b*T_FRAMES + t];
    float f0nz = (f0v > 0.0f) ? f0v : 80.0f;     // SR/NUM_BANDS*0.5
    int rowbase = (t*BATCH + b) * DIN;
    for (int j = tid; j < 300; j += 256) {
        float m = 0.5f * (float)(j + 1);          // 0.5, 1.0, ..., 150.0
        float harm = f0nz * m;
        float r = harm / 11.71875f;               // FREQ_INTERVAL, IEEE div to match jnp
        int k = (int)rintf(r);                    // round-half-even, matches jnp.round
        k = min(max(k, 0), 1024);
        float p = 0.0f;
        if (k < 1024) { float2 X = S[k]; p = X.x*X.x + X.y*X.y; }  // spec[...,1024] zeroed
        g_feat[rowbase + j] = (logf(p + 1e-8f) + 18.0f) / 23.0f;
    }
    if (tid == 0) g_feat[rowbase + 300] = logf(f0nz);
}

// ---------------------------- input pre-GEMM ------------------------------
// pre[row][g'] = bias[g'] + sum_k feat[row][k] * wihT[k][g']
__global__ __launch_bounds__(256) void pre_gemm_kernel()
{
    __shared__ float s_feat[16 * DIN];
    int t = blockIdx.x;
    int cb = blockIdx.y * 512;
    int tid = threadIdx.x;

    int base = t * 16 * DIN;
    for (int i = tid; i < 16*DIN; i += 256) s_feat[i] = g_feat[base + i];
    __syncthreads();

    int cl = (tid & 127) * 4 + cb;   // 4 consecutive cols
    int rh = tid >> 7;               // row half: rows rh*8 .. rh*8+7
    float4 acc[8];
    float4 bias = *(const float4*)&g_bias[cl];
    #pragma unroll
    for (int r = 0; r < 8; r++) acc[r] = bias;

    const float* fb = s_feat + rh*8*DIN;
    for (int k = 0; k < DIN; k++) {
        float4 w = *(const float4*)&g_wihT[k*1024 + cl];
        #pragma unroll
        for (int r = 0; r < 8; r++) {
            float f = fb[r*DIN + k];
            acc[r].x += f*w.x; acc[r].y += f*w.y; acc[r].z += f*w.z; acc[r].w += f*w.w;
        }
    }
    #pragma unroll
    for (int r = 0; r < 8; r++) {
        int row = t*16 + rh*8 + r;
        *(float4*)&g_pre[row*1024 + cl] = acc[r];
    }
}

// ------------------------------ bi-LSTM ----------------------------------
__device__ __forceinline__ float sigm(float v) { return 1.0f / (1.0f + expf(-v)); }

__global__ __launch_bounds__(512) void lstm_kernel()
{
    int d = blockIdx.x >> 4;       // 0 fwd, 1 bwd
    int b = blockIdx.x & 15;
    int g = threadIdx.x;           // gate row 0..511

    __shared__ float4 h4[32];      // current h (128 floats)
    __shared__ float  z_sh[512];

    if (g < 32) h4[g] = make_float4(0.f, 0.f, 0.f, 0.f);
    float c_state = 0.0f;
    __syncthreads();

    const float4* W = g_whh4 + d * 16384;      // [k4*512 + g]
    const float*  preB = g_pre + d*512 + g;

    for (int s = 0; s < T_FRAMES; s++) {
        int t = d ? (T_FRAMES - 1 - s) : s;
        float pv = preB[(t*BATCH + b) * 1024];

        float acc = 0.0f;
        #pragma unroll 8
        for (int k4 = 0; k4 < 32; k4++) {
            float4 w = W[k4*512 + g];
            float4 hv = h4[k4];
            acc += w.x*hv.x + w.y*hv.y + w.z*hv.z + w.w*hv.w;
        }
        z_sh[g] = pv + acc;
        __syncthreads();

        if (g < HID) {
            float zi = z_sh[g], zf = z_sh[g+128], zg = z_sh[g+256], zo = z_sh[g+384];
            c_state = sigm(zf)*c_state + sigm(zi)*tanhf(zg);
            float h = sigm(zo)*tanhf(c_state);
            ((float*)h4)[g] = h;
            g_hcat[(t*BATCH + b)*256 + d*HID + g] = h;
        }
        __syncthreads();
    }
}

// ----------------------- LayerNorm + output GEMM --------------------------
__global__ __launch_bounds__(256) void final_kernel(const float* __restrict__ ln_g,
                                                    const float* __restrict__ ln_b,
                                                    const float* __restrict__ out_b,
                                                    float* __restrict__ out)
{
    __shared__ float sh[16*256];
    __shared__ float s_sum[256], s_sq[256];
    __shared__ float s_mu[16], s_rstd[16];

    int t = blockIdx.x, tid = threadIdx.x;
    for (int i = tid; i < 4096; i += 256) sh[i] = g_hcat[t*4096 + i];
    __syncthreads();

    {
        int row = tid >> 4, seg = tid & 15;
        float sm = 0.f, sq = 0.f;
        const float* p = sh + row*256 + seg*16;
        #pragma unroll
        for (int u = 0; u < 16; u++) { float v = p[u]; sm += v; sq += v*v; }
        s_sum[tid] = sm; s_sq[tid] = sq;
    }
    __syncthreads();
    if (tid < 16) {
        float sm = 0.f, sq = 0.f;
        #pragma unroll
        for (int u = 0; u < 16; u++) { sm += s_sum[tid*16 + u]; sq += s_sq[tid*16 + u]; }
        float mu = sm * (1.0f/256.0f);
        float var = sq * (1.0f/256.0f) - mu*mu;
        s_mu[tid] = mu;
        s_rstd[tid] = rsqrtf(var + 1e-5f);
    }
    __syncthreads();
    for (int i = tid; i < 4096; i += 256) {
        int r = i >> 8, k = i & 255;
        sh[i] = (sh[i] - s_mu[r]) * s_rstd[r] * ln_g[k] + ln_b[k];
    }
    __syncthreads();

    int col = tid & 63, rg = tid >> 6;      // rg handles 4 batch rows
    float acc[4];
    float bb = out_b[col];
    #pragma unroll
    for (int r = 0; r < 4; r++) acc[r] = bb;
    for (int k = 0; k < 256; k++) {
        float w = g_owT[k*64 + col];
        #pragma unroll
        for (int r = 0; r < 4; r++) acc[r] += sh[(rg*4 + r)*256 + k] * w;
    }
    #pragma unroll
    for (int r = 0; r < 4; r++) {
        int b = rg*4 + r;
        out[(b*T_FRAMES + t)*DOUTN + col] = acc[r];
    }
}

// ------------------------------ launcher ----------------------------------
extern "C" void kernel_launch(void* const* d_in, const int* in_sizes, int n_in,
                              void* d_out, int out_size)
{
    const float* x     = (const float*)d_in[0];
    const float* f0    = (const float*)d_in[1];
    const float* wihf  = (const float*)d_in[2];
    const float* whhf  = (const float*)d_in[3];
    const float* bf    = (const float*)d_in[4];
    const float* wihb  = (const float*)d_in[5];
    const float* whhb  = (const float*)d_in[6];
    const float* bb    = (const float*)d_in[7];
    const float* lng   = (const float*)d_in[8];
    const float* lnb   = (const float*)d_in[9];
    const float* outw  = (const float*)d_in[10];
    const float* outb  = (const float*)d_in[11];
    float* out = (float*)d_out;

    prep_kernel<<<256, 256>>>(wihf, whhf, bf, wihb, whhb, bb, outw);
    stft_kernel<<<dim3(T_FRAMES, BATCH), 256>>>(x, f0);
    pre_gemm_kernel<<<dim3(T_FRAMES, 2), 256>>>();
    lstm_kernel<<<32, 512>>>();
    final_kernel<<<T_FRAMES, 256>>>(lng, lnb, outb, out);
}

// round 5
// speedup vs baseline: 1.4090x; 1.4090x over previous
#include <cuda_runtime.h>
#include <cstdint>
#include <math.h>

#define T_FRAMES 1001
#define BATCH    16
#define LSIG     240000
#define HOP      240
#define DIN      301
#define HID      128
#define DOUTN    64
#define NROWS    (T_FRAMES*BATCH)   // 16016

typedef unsigned long long ull;
typedef unsigned int u32;

// ------------------------- static device scratch -------------------------
__device__ float2 g_tw[1024];                  // FFT twiddles e^{-2pi i k/2048}
__device__ float  g_feat[NROWS * DIN];         // features [row=t*16+b][301]
__device__ float  g_wihT[DIN * 1024];          // transposed input weights [k][g]
__device__ float  g_bias[1024];
__device__ float  g_pre[NROWS * 1024];         // pre-activations [row][1024]
__device__ float2 g_whhP[2 * 64 * 512];        // [d][k2][g] = (W[g][2k2], W[g][2k2+1])
__device__ float  g_hcat[NROWS * 256];         // [row][fwd 0..127 | bwd 128..255]
__device__ float  g_owT[256 * 64];             // out_w transposed [k][o]

// ------------------------------ prep kernel ------------------------------
__global__ void prep_kernel(const float* __restrict__ wihf, const float* __restrict__ whhf,
                            const float* __restrict__ bf,   const float* __restrict__ wihb,
                            const float* __restrict__ whhb, const float* __restrict__ bb,
                            const float* __restrict__ outw)
{
    int tid = blockIdx.x * blockDim.x + threadIdx.x;
    int nth = gridDim.x * blockDim.x;

    for (int k = tid; k < 1024; k += nth) {
        float s, c;
        sincospif((float)k * (1.0f/1024.0f), &s, &c);
        g_tw[k] = make_float2(c, -s);
    }
    for (int i = tid; i < DIN*1024; i += nth) {
        int g = i & 1023, k = i >> 10;
        g_wihT[i] = (g < 512) ? wihf[g*DIN + k] : wihb[(g-512)*DIN + k];
    }
    for (int g = tid; g < 1024; g += nth)
        g_bias[g] = (g < 512) ? bf[g] : bb[g-512];
    // w_hh pairs: [d][k2][g] -> (W[g][2k2], W[g][2k2+1])
    for (int i = tid; i < 2*64*512; i += nth) {
        int d = i >> 15;
        int k2 = (i >> 9) & 63;
        int g = i & 511;
        const float* W = d ? whhb : whhf;
        g_whhP[i] = make_float2(W[g*HID + 2*k2], W[g*HID + 2*k2 + 1]);
    }
    for (int i = tid; i < 256*64; i += nth) {
        int o = i & 63, k = i >> 6;
        g_owT[i] = outw[o*256 + k];
    }
}

// ---------------------- STFT + harmonic feature kernel --------------------
__global__ __launch_bounds__(256) void stft_kernel(const float* __restrict__ x,
                                                   const float* __restrict__ f0)
{
    __shared__ float2 S[2048];
    int t = blockIdx.x, b = blockIdx.y, tid = threadIdx.x;
    const float* xb = x + b * LSIG;

    for (int j = tid; j < 2048; j += 256) {
        int q = t*HOP + j - 1024;
        if (q < 0) q = -q;
        else if (q >= LSIG) q = 2*LSIG - 2 - q;
        float v = xb[q];
        int jw = j - 544;
        float wv = (jw >= 0 && jw < 960) ? (0.5f - 0.5f*cospif((float)jw * (1.0f/480.0f))) : 0.0f;
        int rev = __brev((unsigned)j) >> 21;
        S[rev] = make_float2(v*wv, 0.0f);
    }
    __syncthreads();

    #pragma unroll
    for (int s = 1; s <= 11; s++) {
        int half = 1 << (s-1);
        int tshift = 11 - s;
        for (int idx = tid; idx < 1024; idx += 256) {
            int pos = idx & (half - 1);
            int grp = idx >> (s-1);
            int i0 = (grp << s) + pos;
            int i1 = i0 + half;
            float2 tw = g_tw[pos << tshift];
            float2 u = S[i0], v = S[i1];
            float tr = tw.x*v.x - tw.y*v.y;
            float ti = tw.x*v.y + tw.y*v.x;
            S[i0] = make_float2(u.x + tr, u.y + ti);
            S[i1] = make_float2(u.x - tr, u.y - ti);
        }
        __syncthreads();
    }

    float f0v = f0[b*T_FRAMES + t];
    float f0nz = (f0v > 0.0f) ? f0v : 80.0f;
    int rowbase = (t*BATCH + b) * DIN;
    for (int j = tid; j < 300; j += 256) {
        float m = 0.5f * (float)(j + 1);
        float harm = f0nz * m;
        float r = harm / 11.71875f;
        int k = (int)rintf(r);
        k = min(max(k, 0), 1024);
        float p = 0.0f;
        if (k < 1024) { float2 X = S[k]; p = X.x*X.x + X.y*X.y; }
        g_feat[rowbase + j] = (logf(p + 1e-8f) + 18.0f) / 23.0f;
    }
    if (tid == 0) g_feat[rowbase + 300] = logf(f0nz);
}

// ---------------------------- input pre-GEMM ------------------------------
__global__ __launch_bounds__(256) void pre_gemm_kernel()
{
    __shared__ float s_feat[16 * DIN];
    int t = blockIdx.x;
    int cb = blockIdx.y * 512;
    int tid = threadIdx.x;

    int base = t * 16 * DIN;
    for (int i = tid; i < 16*DIN; i += 256) s_feat[i] = g_feat[base + i];
    __syncthreads();

    int cl = (tid & 127) * 4 + cb;
    int rh = tid >> 7;
    float4 acc[8];
    float4 bias = *(const float4*)&g_bias[cl];
    #pragma unroll
    for (int r = 0; r < 8; r++) acc[r] = bias;

    const float* fb = s_feat + rh*8*DIN;
    for (int k = 0; k < DIN; k++) {
        float4 w = *(const float4*)&g_wihT[k*1024 + cl];
        #pragma unroll
        for (int r = 0; r < 8; r++) {
            float f = fb[r*DIN + k];
            acc[r].x += f*w.x; acc[r].y += f*w.y; acc[r].z += f*w.z; acc[r].w += f*w.w;
        }
    }
    #pragma unroll
    for (int r = 0; r < 8; r++) {
        int row = t*16 + rh*8 + r;
        *(float4*)&g_pre[row*1024 + cl] = acc[r];
    }
}

// ------------------------------ bi-LSTM ----------------------------------
__device__ __forceinline__ float sigm(float v) { return 1.0f / (1.0f + expf(-v)); }

__device__ __forceinline__ ull ffma2(ull a, ull b, ull c) {
    ull d;
    asm("fma.rn.f32x2 %0, %1, %2, %3;" : "=l"(d) : "l"(a), "l"(b), "l"(c));
    return d;
}
__device__ __forceinline__ float2 u2f2(ull a) {
    float2 f;
    asm("mov.b64 {%0, %1}, %2;" : "=f"(f.x), "=f"(f.y) : "l"(a));
    return f;
}
__device__ __forceinline__ void st_remote_f32(u32 laddr, u32 peer, float v) {
    u32 r;
    asm volatile("mapa.shared::cluster.u32 %0, %1, %2;" : "=r"(r) : "r"(laddr), "r"(peer));
    asm volatile("st.shared::cluster.f32 [%0], %1;" :: "r"(r), "f"(v) : "memory");
}
#define CLUSTER_SYNC() do { \
    asm volatile("barrier.cluster.arrive.aligned;" ::: "memory"); \
    asm volatile("barrier.cluster.wait.aligned;"   ::: "memory"); \
} while (0)

// cluster of 2 CTAs per (b, d): k-dimension split, weights register-resident.
__global__ __launch_bounds__(512, 1) __cluster_dims__(2, 1, 1)
void lstm_kernel()
{
    int cid  = blockIdx.x >> 1;      // 0..31
    int rank = blockIdx.x & 1;       // k-half
    int d = cid >> 4, b = cid & 15;
    int g = threadIdx.x;             // gate row 0..511

    // 64 weights (this rank's k-half of row g) as 32 packed f32x2 registers
    ull w2[32];
    {
        const ull* WP = (const ull*)g_whhP + (size_t)(d*64 + rank*32)*512 + g;
        #pragma unroll
        for (int j = 0; j < 32; j++) w2[j] = WP[j*512];
    }

    __shared__ __align__(16) ull h2_sh[64];     // current h: 128 floats
    __shared__ float part_self[512];
    __shared__ float part_peer[2][512];         // double-buffered by step parity

    if (g < 64) h2_sh[g] = 0ULL;
    float c_state = 0.0f;
    u32 peer_base = (u32)__cvta_generic_to_shared(part_peer);
    __syncthreads();
    CLUSTER_SYNC();   // both CTAs initialized before any remote traffic

    const float* preB = g_pre + d*512;
    float* hcatB = g_hcat + d*HID;

    for (int s = 0; s < T_FRAMES; s++) {
        int t = d ? (T_FRAMES - 1 - s) : s;
        int row = t*BATCH + b;

        // prefetch pre-activations (gate threads) — independent of the dot
        float p0, p1, p2, p3;
        if (g < HID) {
            const float* pr = preB + (size_t)row*1024;
            p0 = pr[g]; p1 = pr[g+128]; p2 = pr[g+256]; p3 = pr[g+384];
        }

        // partial dot over this rank's k-half: 32 packed FFMA2
        ull a0 = 0ULL, a1 = 0ULL, a2 = 0ULL, a3 = 0ULL;
        const ulonglong2* hh = (const ulonglong2*)(h2_sh + rank*32);
        #pragma unroll
        for (int j = 0; j < 8; j++) {
            ulonglong2 hA = hh[2*j], hB = hh[2*j+1];
            a0 = ffma2(w2[4*j+0], hA.x, a0);
            a1 = ffma2(w2[4*j+1], hA.y, a1);
            a2 = ffma2(w2[4*j+2], hB.x, a2);
            a3 = ffma2(w2[4*j+3], hB.y, a3);
        }
        float2 f0v = u2f2(a0), f1v = u2f2(a1), f2v = u2f2(a2), f3v = u2f2(a3);
        float partial = ((f0v.x + f0v.y) + (f1v.x + f1v.y))
                      + ((f2v.x + f2v.y) + (f3v.x + f3v.y));

        part_self[g] = partial;
        st_remote_f32(peer_base + (u32)(s & 1)*2048u + (u32)g*4u, rank ^ 1, partial);

        CLUSTER_SYNC();   // arrive=release orders the DSMEM store; wait=acquire

        if (g < HID) {
            // fixed summation order (k-low half first) -> both ranks bit-identical
            const float* lo = rank ? part_peer[s & 1] : part_self;
            const float* hi = rank ? part_self : part_peer[s & 1];
            float zi = (lo[g]     + hi[g])     + p0;
            float zf = (lo[g+128] + hi[g+128]) + p1;
            float zg = (lo[g+256] + hi[g+256]) + p2;
            float zo = (lo[g+384] + hi[g+384]) + p3;
            c_state = sigm(zf)*c_state + sigm(zi)*tanhf(zg);
            float h = sigm(zo)*tanhf(c_state);
            ((float*)h2_sh)[g] = h;
            if (rank == 0) hcatB[(size_t)row*256 + g] = h;
        }
        __syncthreads();   // h2_sh ready for next step
    }
    CLUSTER_SYNC();
}

// ----------------------- LayerNorm + output GEMM --------------------------
__global__ __launch_bounds__(256) void final_kernel(const float* __restrict__ ln_g,
                                                    const float* __restrict__ ln_b,
                                                    const float* __restrict__ out_b,
                                                    float* __restrict__ out)
{
    __shared__ float sh[16*256];
    __shared__ float s_sum[256], s_sq[256];
    __shared__ float s_mu[16], s_rstd[16];

    int t = blockIdx.x, tid = threadIdx.x;
    for (int i = tid; i < 4096; i += 256) sh[i] = g_hcat[t*4096 + i];
    __syncthreads();

    {
        int row = tid >> 4, seg = tid & 15;
        float sm = 0.f, sq = 0.f;
        const float* p = sh + row*256 + seg*16;
        #pragma unroll
        for (int u = 0; u < 16; u++) { float v = p[u]; sm += v; sq += v*v; }
        s_sum[tid] = sm; s_sq[tid] = sq;
    }
    __syncthreads();
    if (tid < 16) {
        float sm = 0.f, sq = 0.f;
        #pragma unroll
        for (int u = 0; u < 16; u++) { sm += s_sum[tid*16 + u]; sq += s_sq[tid*16 + u]; }
        float mu = sm * (1.0f/256.0f);
        float var = sq * (1.0f/256.0f) - mu*mu;
        s_mu[tid] = mu;
        s_rstd[tid] = rsqrtf(var + 1e-5f);
    }
    __syncthreads();
    for (int i = tid; i < 4096; i += 256) {
        int r = i >> 8, k = i & 255;
        sh[i] = (sh[i] - s_mu[r]) * s_rstd[r] * ln_g[k] + ln_b[k];
    }
    __syncthreads();

    int col = tid & 63, rg = tid >> 6;
    float acc[4];
    float bb = out_b[col];
    #pragma unroll
    for (int r = 0; r < 4; r++) acc[r] = bb;
    for (int k = 0; k < 256; k++) {
        float w = g_owT[k*64 + col];
        #pragma unroll
        for (int r = 0; r < 4; r++) acc[r] += sh[(rg*4 + r)*256 + k] * w;
    }
    #pragma unroll
    for (int r = 0; r < 4; r++) {
        int b = rg*4 + r;
        out[(b*T_FRAMES + t)*DOUTN + col] = acc[r];
    }
}

// ------------------------------ launcher ----------------------------------
extern "C" void kernel_launch(void* const* d_in, const int* in_sizes, int n_in,
                              void* d_out, int out_size)
{
    const float* x     = (const float*)d_in[0];
    const float* f0    = (const float*)d_in[1];
    const float* wihf  = (const float*)d_in[2];
    const float* whhf  = (const float*)d_in[3];
    const float* bf    = (const float*)d_in[4];
    const float* wihb  = (const float*)d_in[5];
    const float* whhb  = (const float*)d_in[6];
    const float* bb    = (const float*)d_in[7];
    const float* lng   = (const float*)d_in[8];
    const float* lnb   = (const float*)d_in[9];
    const float* outw  = (const float*)d_in[10];
    const float* outb  = (const float*)d_in[11];
    float* out = (float*)d_out;

    prep_kernel<<<256, 256>>>(wihf, whhf, bf, wihb, whhb, bb, outw);
    stft_kernel<<<dim3(T_FRAMES, BATCH), 256>>>(x, f0);
    pre_gemm_kernel<<<dim3(T_FRAMES, 2), 256>>>();
    lstm_kernel<<<64, 512>>>();
    final_kernel<<<T_FRAMES, 256>>>(lng, lnb, outb, out);
}

// round 6
// speedup vs baseline: 1.7997x; 1.2773x over previous
#include <cuda_runtime.h>
#include <cstdint>
#include <math.h>

#define T_FRAMES 1001
#define BATCH    16
#define LSIG     240000
#define HOP      240
#define DIN      301
#define HID      128
#define DOUTN    64
#define NROWS    (T_FRAMES*BATCH)   // 16016

typedef unsigned long long ull;
typedef unsigned int u32;

// ------------------------- static device scratch -------------------------
__device__ float2 g_tw[1024];                  // twiddles e^{-2pi i k/2048}
__device__ float  g_feat[NROWS * DIN];         // features [row=t*16+b][301]
__device__ float  g_wihT[DIN * 1024];          // transposed input weights [k][g]
__device__ float  g_bias[1024];
__device__ float  g_pre[NROWS * 1024];         // pre-activations [row][1024]
__device__ float2 g_whhP[2 * 64 * 512];        // [d][k2][g] = (W[g][2k2], W[g][2k2+1])
__device__ float  g_hcat[NROWS * 256];         // [row][fwd 0..127 | bwd 128..255]
__device__ float  g_owT[256 * 64];             // out_w transposed [k][o]

// ------------------------------ prep kernel ------------------------------
__global__ void prep_kernel(const float* __restrict__ wihf, const float* __restrict__ whhf,
                            const float* __restrict__ bf,   const float* __restrict__ wihb,
                            const float* __restrict__ whhb, const float* __restrict__ bb,
                            const float* __restrict__ outw)
{
    int tid = blockIdx.x * blockDim.x + threadIdx.x;
    int nth = gridDim.x * blockDim.x;

    for (int k = tid; k < 1024; k += nth) {
        float s, c;
        sincospif((float)k * (1.0f/1024.0f), &s, &c);
        g_tw[k] = make_float2(c, -s);
    }
    for (int i = tid; i < DIN*1024; i += nth) {
        int g = i & 1023, k = i >> 10;
        g_wihT[i] = (g < 512) ? wihf[g*DIN + k] : wihb[(g-512)*DIN + k];
    }
    for (int g = tid; g < 1024; g += nth)
        g_bias[g] = (g < 512) ? bf[g] : bb[g-512];
    for (int i = tid; i < 2*64*512; i += nth) {
        int d = i >> 15;
        int k2 = (i >> 9) & 63;
        int g = i & 511;
        const float* W = d ? whhb : whhf;
        g_whhP[i] = make_float2(W[g*HID + 2*k2], W[g*HID + 2*k2 + 1]);
    }
    for (int i = tid; i < 256*64; i += nth) {
        int o = i & 63, k = i >> 6;
        g_owT[i] = outw[o*256 + k];
    }
}

// ---------------------- STFT (real-packed) + features ---------------------
__device__ __forceinline__ float wsamp(const float* __restrict__ xb, int t, int j)
{
    int q = t*HOP + j - 1024;
    if (q < 0) q = -q;
    else if (q >= LSIG) q = 2*LSIG - 2 - q;
    int jw = j - 544;
    float wv = (jw >= 0 && jw < 960) ? (0.5f - 0.5f*cospif((float)jw * (1.0f/480.0f))) : 0.0f;
    return xb[q] * wv;
}

__global__ __launch_bounds__(256) void stft_kernel(const float* __restrict__ x,
                                                   const float* __restrict__ f0)
{
    __shared__ float2 S[1024];
    int t = blockIdx.x, b = blockIdx.y, tid = threadIdx.x;
    const float* xb = x + b * LSIG;

    // pack even/odd windowed samples into 1024 complex, bit-reversed (10 bit)
    for (int n = tid; n < 1024; n += 256) {
        float v0 = wsamp(xb, t, 2*n);
        float v1 = wsamp(xb, t, 2*n + 1);
        int rev = __brev((unsigned)n) >> 22;
        S[rev] = make_float2(v0, v1);
    }
    __syncthreads();

    // 10-stage radix-2 DIT on 1024 complex
    #pragma unroll
    for (int s = 1; s <= 10; s++) {
        int half = 1 << (s-1);
        for (int idx = tid; idx < 512; idx += 256) {
            int pos = idx & (half - 1);
            int grp = idx >> (s-1);
            int i0 = (grp << s) + pos;
            int i1 = i0 + half;
            float2 tw = g_tw[pos << (11 - s)];
            float2 u = S[i0], v = S[i1];
            float tr = tw.x*v.x - tw.y*v.y;
            float ti = tw.x*v.y + tw.y*v.x;
            S[i0] = make_float2(u.x + tr, u.y + ti);
            S[i1] = make_float2(u.x - tr, u.y - ti);
        }
        __syncthreads();
    }

    // harmonic gather with real-FFT unpack:
    // X[k] = Xe[k] + e^{-i pi k/1024} * Xo[k]
    float f0v = f0[b*T_FRAMES + t];
    float f0nz = (f0v > 0.0f) ? f0v : 80.0f;
    int rowbase = (t*BATCH + b) * DIN;
    for (int j = tid; j < 300; j += 256) {
        float m = 0.5f * (float)(j + 1);
        float harm = f0nz * m;
        float r = harm / 11.71875f;
        int k = (int)rintf(r);
        k = min(max(k, 0), 1024);
        float p = 0.0f;
        if (k < 1024) {
            int kr = (1024 - k) & 1023;
            float2 a = S[k];
            float2 zr = S[kr];
            float br = zr.x, bi = -zr.y;                 // conj(Z[N-k])
            float xer = 0.5f*(a.x + br), xei = 0.5f*(a.y + bi);
            float dr = a.x - br, di = a.y - bi;
            float xo_r = 0.5f*di, xo_i = -0.5f*dr;       // -i*(a-b)/2
            float sn, cs;
            sincospif((float)k * (1.0f/1024.0f), &sn, &cs);
            float wr = cs, wi = -sn;
            float Xr = xer + wr*xo_r - wi*xo_i;
            float Xi = xei + wr*xo_i + wi*xo_r;
            p = Xr*Xr + Xi*Xi;
        }
        g_feat[rowbase + j] = (logf(p + 1e-8f) + 18.0f) / 23.0f;
    }
    if (tid == 0) g_feat[rowbase + 300] = logf(f0nz);
}

// ---------------------------- input pre-GEMM ------------------------------
__global__ __launch_bounds__(256) void pre_gemm_kernel()
{
    __shared__ float s_feat[16 * DIN];
    int t = blockIdx.x;
    int cb = blockIdx.y * 512;
    int tid = threadIdx.x;

    int base = t * 16 * DIN;
    for (int i = tid; i < 16*DIN; i += 256) s_feat[i] = g_feat[base + i];
    __syncthreads();

    int cl = (tid & 127) * 4 + cb;
    int rh = tid >> 7;
    float4 acc[8];
    float4 bias = *(const float4*)&g_bias[cl];
    #pragma unroll
    for (int r = 0; r < 8; r++) acc[r] = bias;

    const float* fb = s_feat + rh*8*DIN;
    for (int k = 0; k < DIN; k++) {
        float4 w = *(const float4*)&g_wihT[k*1024 + cl];
        #pragma unroll
        for (int r = 0; r < 8; r++) {
            float f = fb[r*DIN + k];
            acc[r].x += f*w.x; acc[r].y += f*w.y; acc[r].z += f*w.z; acc[r].w += f*w.w;
        }
    }
    #pragma unroll
    for (int r = 0; r < 8; r++) {
        int row = t*16 + rh*8 + r;
        *(float4*)&g_pre[row*1024 + cl] = acc[r];
    }
}

// ------------------------------ bi-LSTM ----------------------------------
__device__ __forceinline__ float sigm(float v) { return 1.0f / (1.0f + expf(-v)); }

__device__ __forceinline__ ull ffma2(ull a, ull b, ull c) {
    ull d;
    asm("fma.rn.f32x2 %0, %1, %2, %3;" : "=l"(d) : "l"(a), "l"(b), "l"(c));
    return d;
}
__device__ __forceinline__ float2 u2f2(ull a) {
    float2 f;
    asm("mov.b64 {%0, %1}, %2;" : "=f"(f.x), "=f"(f.y) : "l"(a));
    return f;
}
#define CLUSTER_SYNC() do { \
    asm volatile("barrier.cluster.arrive.aligned;" ::: "memory"); \
    asm volatile("barrier.cluster.wait.aligned;"   ::: "memory"); \
} while (0)

// cluster of 2 CTAs per (b, d): k-split, register-resident weights,
// mbarrier/st.async handshake instead of barrier.cluster per step.
__global__ __launch_bounds__(512, 1) __cluster_dims__(2, 1, 1)
void lstm_kernel()
{
    int cid  = blockIdx.x >> 1;      // 0..31
    int rank = blockIdx.x & 1;       // k-half
    int d = cid >> 4, b = cid & 15;
    int g = threadIdx.x;             // gate row 0..511

    // 64 weights (this rank's k-half of row g) as 32 packed f32x2 registers
    ull w2[32];
    {
        const ull* WP = (const ull*)g_whhP + (size_t)(d*64 + rank*32)*512 + g;
        #pragma unroll
        for (int j = 0; j < 32; j++) w2[j] = WP[j*512];
    }

    __shared__ __align__(16) ull   h2_sh[64];          // current h (128 floats)
    __shared__ __align__(16) float partbuf[2][2][512]; // [parity][rank][g]
    __shared__ __align__(8)  ull   s_bar[2];           // parity-indexed mbarriers

    if (g < 64) h2_sh[g] = 0ULL;
    u32 bar_local  = (u32)__cvta_generic_to_shared(s_bar);
    u32 part_local = (u32)__cvta_generic_to_shared(partbuf);
    if (g == 0) {
        asm volatile("mbarrier.init.shared.b64 [%0], 1;" :: "r"(bar_local)     : "memory");
        asm volatile("mbarrier.init.shared.b64 [%0], 1;" :: "r"(bar_local + 8) : "memory");
    }
    float c_state = 0.0f;
    __syncthreads();
    CLUSTER_SYNC();   // peer barriers initialized before any st.async

    // cluster-mapped addresses (hoisted)
    u32 part_self_c, part_peer_c, bar_self_c, bar_peer_c;
    asm("mapa.shared::cluster.u32 %0, %1, %2;" : "=r"(part_self_c) : "r"(part_local), "r"((u32)rank));
    asm("mapa.shared::cluster.u32 %0, %1, %2;" : "=r"(part_peer_c) : "r"(part_local), "r"((u32)(rank^1)));
    asm("mapa.shared::cluster.u32 %0, %1, %2;" : "=r"(bar_self_c)  : "r"(bar_local),  "r"((u32)rank));
    asm("mapa.shared::cluster.u32 %0, %1, %2;" : "=r"(bar_peer_c)  : "r"(bar_local),  "r"((u32)(rank^1)));
    u32 wofs = (u32)rank*2048u + (u32)g*4u;   // my slot: [*][rank][g]

    const float* preB = g_pre + d*512;
    float* hcatB = g_hcat + d*HID;

    for (int s = 0; s < T_FRAMES; s++) {
        int t = d ? (T_FRAMES - 1 - s) : s;
        int row = t*BATCH + b;
        u32 par = (u32)(s & 1);
        u32 ph  = (u32)((s >> 1) & 1);

        // prefetch pre-activations — overlaps the dot
        float p0, p1, p2, p3;
        if (g < HID) {
            const float* pr = preB + (size_t)row*1024;
            p0 = pr[g]; p1 = pr[g+128]; p2 = pr[g+256]; p3 = pr[g+384];
        }

        if (g == 0) {   // this phase expects 2048B self + 2048B peer
            asm volatile("mbarrier.arrive.expect_tx.shared.b64 _, [%0], %1;"
                         :: "r"(bar_local + 8u*par), "r"(4096u) : "memory");
        }

        // partial dot over this rank's k-half: 32 packed FFMA2
        ull a0 = 0ULL, a1 = 0ULL, a2 = 0ULL, a3 = 0ULL;
        const ulonglong2* hh = (const ulonglong2*)(h2_sh + rank*32);
        #pragma unroll
        for (int j = 0; j < 8; j++) {
            ulonglong2 hA = hh[2*j], hB = hh[2*j+1];
            a0 = ffma2(w2[4*j+0], hA.x, a0);
            a1 = ffma2(w2[4*j+1], hA.y, a1);
            a2 = ffma2(w2[4*j+2], hB.x, a2);
            a3 = ffma2(w2[4*j+3], hB.y, a3);
        }
        float2 f0v = u2f2(a0), f1v = u2f2(a1), f2v = u2f2(a2), f3v = u2f2(a3);
        float partial = ((f0v.x + f0v.y) + (f1v.x + f1v.y))
                      + ((f2v.x + f2v.y) + (f3v.x + f3v.y));

        // publish to both CTAs; completion counted on each CTA's bar[par]
        u32 off = par*4096u + wofs;
        u32 v = __float_as_uint(partial);
        asm volatile("st.async.shared::cluster.mbarrier::complete_tx::bytes.u32 [%0], %1, [%2];"
                     :: "r"(part_self_c + off), "r"(v), "r"(bar_self_c + 8u*par) : "memory");
        asm volatile("st.async.shared::cluster.mbarrier::complete_tx::bytes.u32 [%0], %1, [%2];"
                     :: "r"(part_peer_c + off), "r"(v), "r"(bar_peer_c + 8u*par) : "memory");

        // wait for all 4096 bytes of this step
        asm volatile("{\n\t"
                     ".reg .pred P;\n"
                     "LW%=:\n\t"
                     "mbarrier.try_wait.parity.acquire.cluster.shared::cta.b64 P, [%0], %1, 0x989680;\n\t"
                     "@!P bra LW%=;\n\t"
                     "}" :: "r"(bar_local + 8u*par), "r"(ph) : "memory");

        if (g < HID) {
            const float* lo = partbuf[par][0];   // k-low half (rank 0)
            const float* hi = partbuf[par][1];   // k-high half (rank 1)
            float zi = (lo[g]     + hi[g])     + p0;
            float zf = (lo[g+128] + hi[g+128]) + p1;
            float zg = (lo[g+256] + hi[g+256]) + p2;
            float zo = (lo[g+384] + hi[g+384]) + p3;
            c_state = sigm(zf)*c_state + sigm(zi)*tanhf(zg);
            float h = sigm(zo)*tanhf(c_state);
            ((float*)h2_sh)[g] = h;
            if (rank == 0) hcatB[(size_t)row*256 + g] = h;
        }
        __syncthreads();   // h2_sh ready for next step's dot
    }
    CLUSTER_SYNC();        // no CTA exits with peer traffic in flight
}

// ----------------------- LayerNorm + output GEMM --------------------------
__global__ __launch_bounds__(256) void final_kernel(const float* __restrict__ ln_g,
                                                    const float* __restrict__ ln_b,
                                                    const float* __restrict__ out_b,
                                                    float* __restrict__ out)
{
    __shared__ float sh[16*256];
    __shared__ float s_sum[256], s_sq[256];
    __shared__ float s_mu[16], s_rstd[16];

    int t = blockIdx.x, tid = threadIdx.x;
    for (int i = tid; i < 4096; i += 256) sh[i] = g_hcat[t*4096 + i];
    __syncthreads();

    {
        int row = tid >> 4, seg = tid & 15;
        float sm = 0.f, sq = 0.f;
        const float* p = sh + row*256 + seg*16;
        #pragma unroll
        for (int u = 0; u < 16; u++) { float v = p[u]; sm += v; sq += v*v; }
        s_sum[tid] = sm; s_sq[tid] = sq;
    }
    __syncthreads();
    if (tid < 16) {
        float sm = 0.f, sq = 0.f;
        #pragma unroll
        for (int u = 0; u < 16; u++) { sm += s_sum[tid*16 + u]; sq += s_sq[tid*16 + u]; }
        float mu = sm * (1.0f/256.0f);
        float var = sq * (1.0f/256.0f) - mu*mu;
        s_mu[tid] = mu;
        s_rstd[tid] = rsqrtf(var + 1e-5f);
    }
    __syncthreads();
    for (int i = tid; i < 4096; i += 256) {
        int r = i >> 8, k = i & 255;
        sh[i] = (sh[i] - s_mu[r]) * s_rstd[r] * ln_g[k] + ln_b[k];
    }
    __syncthreads();

    int col = tid & 63, rg = tid >> 6;
    float acc[4];
    float bb = out_b[col];
    #pragma unroll
    for (int r = 0; r < 4; r++) acc[r] = bb;
    for (int k = 0; k < 256; k++) {
        float w = g_owT[k*64 + col];
        #pragma unroll
        for (int r = 0; r < 4; r++) acc[r] += sh[(rg*4 + r)*256 + k] * w;
    }
    #pragma unroll
    for (int r = 0; r < 4; r++) {
        int b = rg*4 + r;
        out[(b*T_FRAMES + t)*DOUTN + col] = acc[r];
    }
}

// ------------------------------ launcher ----------------------------------
extern "C" void kernel_launch(void* const* d_in, const int* in_sizes, int n_in,
                              void* d_out, int out_size)
{
    const float* x     = (const float*)d_in[0];
    const float* f0    = (const float*)d_in[1];
    const float* wihf  = (const float*)d_in[2];
    const float* whhf  = (const float*)d_in[3];
    const float* bf    = (const float*)d_in[4];
    const float* wihb  = (const float*)d_in[5];
    const float* whhb  = (const float*)d_in[6];
    const float* bb    = (const float*)d_in[7];
    const float* lng   = (const float*)d_in[8];
    const float* lnb   = (const float*)d_in[9];
    const float* outw  = (const float*)d_in[10];
    const float* outb  = (const float*)d_in[11];
    float* out = (float*)d_out;

    prep_kernel<<<256, 256>>>(wihf, whhf, bf, wihb, whhb, bb, outw);
    stft_kernel<<<dim3(T_FRAMES, BATCH), 256>>>(x, f0);
    pre_gemm_kernel<<<dim3(T_FRAMES, 2), 256>>>();
    lstm_kernel<<<64, 512>>>();
    final_kernel<<<T_FRAMES, 256>>>(lng, lnb, outb, out);
}

// round 9
// speedup vs baseline: 3.2677x; 1.8157x over previous
#include <cuda_runtime.h>
#include <cstdint>
#include <math.h>

#define T_FRAMES 1001
#define BATCH    16
#define LSIG     240000
#define HOP      240
#define DIN      301
#define HID      128
#define DOUTN    64
#define NROWS    (T_FRAMES*BATCH)   // 16016

typedef unsigned long long ull;
typedef unsigned int u32;

// ------------------------- static device scratch -------------------------
__device__ float2 g_tw[1024];                  // twiddles e^{-2pi i k/2048}
__device__ float  g_feat[NROWS * DIN];         // features [row=t*16+b][301]
__device__ float  g_wihT[DIN * 1024];          // transposed input weights [k][g]
__device__ float  g_bias[1024];
__device__ float  g_pre[NROWS * 1024];         // pre-activations [row][1024]
__device__ float2 g_whhP[2 * 64 * 512];        // [d][k2][g] = (W[g][2k2], W[g][2k2+1])
__device__ float  g_hcat[NROWS * 256];         // [row][fwd 0..127 | bwd 128..255]
__device__ float  g_owT[256 * 64];             // out_w transposed [k][o]

// ------------------------------ prep kernel ------------------------------
__global__ void prep_kernel(const float* __restrict__ wihf, const float* __restrict__ whhf,
                            const float* __restrict__ bf,   const float* __restrict__ wihb,
                            const float* __restrict__ whhb, const float* __restrict__ bb,
                            const float* __restrict__ outw)
{
    int tid = blockIdx.x * blockDim.x + threadIdx.x;
    int nth = gridDim.x * blockDim.x;

    for (int k = tid; k < 1024; k += nth) {
        float s, c;
        sincospif((float)k * (1.0f/1024.0f), &s, &c);
        g_tw[k] = make_float2(c, -s);
    }
    for (int i = tid; i < DIN*1024; i += nth) {
        int g = i & 1023, k = i >> 10;
        g_wihT[i] = (g < 512) ? wihf[g*DIN + k] : wihb[(g-512)*DIN + k];
    }
    for (int g = tid; g < 1024; g += nth)
        g_bias[g] = (g < 512) ? bf[g] : bb[g-512];
    for (int i = tid; i < 2*64*512; i += nth) {
        int d = i >> 15;
        int k2 = (i >> 9) & 63;
        int g = i & 511;
        const float* W = d ? whhb : whhf;
        g_whhP[i] = make_float2(W[g*HID + 2*k2], W[g*HID + 2*k2 + 1]);
    }
    for (int i = tid; i < 256*64; i += nth) {
        int o = i & 63, k = i >> 6;
        g_owT[i] = outw[o*256 + k];
    }
}

// ---------------------- STFT (real-packed) + features ---------------------
__device__ __forceinline__ float wsamp(const float* __restrict__ xb, int t, int j)
{
    int q = t*HOP + j - 1024;
    if (q < 0) q = -q;
    else if (q >= LSIG) q = 2*LSIG - 2 - q;
    int jw = j - 544;
    float wv = (jw >= 0 && jw < 960) ? (0.5f - 0.5f*cospif((float)jw * (1.0f/480.0f))) : 0.0f;
    return xb[q] * wv;
}

__global__ __launch_bounds__(256) void stft_kernel(const float* __restrict__ x,
                                                   const float* __restrict__ f0)
{
    __shared__ float2 S[1024];
    int t = blockIdx.x, b = blockIdx.y, tid = threadIdx.x;
    const float* xb = x + b * LSIG;

    // pack even/odd windowed samples into 1024 complex, bit-reversed (10 bit)
    for (int n = tid; n < 1024; n += 256) {
        float v0 = wsamp(xb, t, 2*n);
        float v1 = wsamp(xb, t, 2*n + 1);
        int rev = __brev((unsigned)n) >> 22;
        S[rev] = make_float2(v0, v1);
    }
    __syncthreads();

    // 10-stage radix-2 DIT on 1024 complex
    #pragma unroll
    for (int s = 1; s <= 10; s++) {
        int half = 1 << (s-1);
        for (int idx = tid; idx < 512; idx += 256) {
            int pos = idx & (half - 1);
            int grp = idx >> (s-1);
            int i0 = (grp << s) + pos;
            int i1 = i0 + half;
            float2 tw = g_tw[pos << (11 - s)];
            float2 u = S[i0], v = S[i1];
            float tr = tw.x*v.x - tw.y*v.y;
            float ti = tw.x*v.y + tw.y*v.x;
            S[i0] = make_float2(u.x + tr, u.y + ti);
            S[i1] = make_float2(u.x - tr, u.y - ti);
        }
        __syncthreads();
    }

    // harmonic gather with real-FFT unpack: X[k] = Xe[k] + e^{-i pi k/1024} Xo[k]
    float f0v = f0[b*T_FRAMES + t];
    float f0nz = (f0v > 0.0f) ? f0v : 80.0f;
    int rowbase = (t*BATCH + b) * DIN;
    for (int j = tid; j < 300; j += 256) {
        float m = 0.5f * (float)(j + 1);
        float harm = f0nz * m;
        float r = harm / 11.71875f;
        int k = (int)rintf(r);
        k = min(max(k, 0), 1024);
        float p = 0.0f;
        if (k < 1024) {
            int kr = (1024 - k) & 1023;
            float2 a = S[k];
            float2 zr = S[kr];
            float br = zr.x, bi = -zr.y;                 // conj(Z[N-k])
            float xer = 0.5f*(a.x + br), xei = 0.5f*(a.y + bi);
            float dr = a.x - br, di = a.y - bi;
            float xo_r = 0.5f*di, xo_i = -0.5f*dr;       // -i*(a-b)/2
            float sn, cs;
            sincospif((float)k * (1.0f/1024.0f), &sn, &cs);
            float wr = cs, wi = -sn;
            float Xr = xer + wr*xo_r - wi*xo_i;
            float Xi = xei + wr*xo_i + wi*xo_r;
            p = Xr*Xr + Xi*Xi;
        }
        g_feat[rowbase + j] = (logf(p + 1e-8f) + 18.0f) / 23.0f;
    }
    if (tid == 0) g_feat[rowbase + 300] = logf(f0nz);
}

// ---------------------------- input pre-GEMM ------------------------------
__global__ __launch_bounds__(256) void pre_gemm_kernel()
{
    __shared__ float s_feat[16 * DIN];
    int t = blockIdx.x;
    int cb = blockIdx.y * 512;
    int tid = threadIdx.x;

    int base = t * 16 * DIN;
    for (int i = tid; i < 16*DIN; i += 256) s_feat[i] = g_feat[base + i];
    __syncthreads();

    int cl = (tid & 127) * 4 + cb;
    int rh = tid >> 7;
    float4 acc[8];
    float4 bias = *(const float4*)&g_bias[cl];
    #pragma unroll
    for (int r = 0; r < 8; r++) acc[r] = bias;

    const float* fb = s_feat + rh*8*DIN;
    for (int k = 0; k < DIN; k++) {
        float4 w = *(const float4*)&g_wihT[k*1024 + cl];
        #pragma unroll
        for (int r = 0; r < 8; r++) {
            float f = fb[r*DIN + k];
            acc[r].x += f*w.x; acc[r].y += f*w.y; acc[r].z += f*w.z; acc[r].w += f*w.w;
        }
    }
    #pragma unroll
    for (int r = 0; r < 8; r++) {
        int row = t*16 + rh*8 + r;
        *(float4*)&g_pre[row*1024 + cl] = acc[r];
    }
}

// ------------------------------ bi-LSTM ----------------------------------
// fast, overflow-safe sigmoid/tanh via MUFU (EX2 + RCP), rel err ~1e-6
__device__ __forceinline__ float fsigm(float x) {
    float e = __expf(-fabsf(x));
    float inv = __fdividef(1.0f, 1.0f + e);
    return (x >= 0.0f) ? inv : e * inv;
}
__device__ __forceinline__ float ftanh(float x) {
    float e = __expf(-2.0f * fabsf(x));
    float r = __fdividef(1.0f - e, 1.0f + e);
    return copysignf(r, x);
}

__device__ __forceinline__ ull ffma2(ull a, ull b, ull c) {
    ull d;
    asm("fma.rn.f32x2 %0, %1, %2, %3;" : "=l"(d) : "l"(a), "l"(b), "l"(c));
    return d;
}
__device__ __forceinline__ float2 u2f2(ull a) {
    float2 f;
    asm("mov.b64 {%0, %1}, %2;" : "=f"(f.x), "=f"(f.y) : "l"(a));
    return f;
}
#define CLUSTER_SYNC() do { \
    asm volatile("barrier.cluster.arrive.aligned;" ::: "memory"); \
    asm volatile("barrier.cluster.wait.aligned;"   ::: "memory"); \
} while (0)

// cluster of 2 CTAs per (b, d): k-split, register-resident weights.
// Per-step exchange = ONE 2048B cp.async.bulk (smem -> peer smem) completing
// on the peer's parity mbarrier; expects armed 2 steps ahead.
__global__ __launch_bounds__(512, 1) __cluster_dims__(2, 1, 1)
void lstm_kernel()
{
    int cid  = blockIdx.x >> 1;      // 0..31
    int rank = blockIdx.x & 1;       // k-half
    int d = cid >> 4, b = cid & 15;
    int g = threadIdx.x;             // gate row 0..511

    // 64 weights (this rank's k-half of row g) as 32 packed f32x2 registers
    ull w2[32];
    {
        const ull* WP = (const ull*)g_whhP + (size_t)(d*64 + rank*32)*512 + g;
        #pragma unroll
        for (int j = 0; j < 32; j++) w2[j] = WP[j*512];
    }

    __shared__ __align__(16) ull   h2_sh[64];          // current h (128 floats)
    __shared__ __align__(16) float partbuf[2][2][512]; // [parity][src-rank][g]
    __shared__ __align__(8)  ull   s_bar[2];           // parity-indexed mbarriers

    if (g < 64) h2_sh[g] = 0ULL;
    u32 bar_local  = (u32)__cvta_generic_to_shared(s_bar);
    u32 part_local = (u32)__cvta_generic_to_shared(partbuf);
    if (g == 0) {
        asm volatile("mbarrier.init.shared.b64 [%0], 1;" :: "r"(bar_local)     : "memory");
        asm volatile("mbarrier.init.shared.b64 [%0], 1;" :: "r"(bar_local + 8) : "memory");
        // arm steps 0 and 1 (2048B peer bytes each) before any peer traffic
        asm volatile("mbarrier.arrive.expect_tx.shared.b64 _, [%0], %1;"
                     :: "r"(bar_local),     "r"(2048u) : "memory");
        asm volatile("mbarrier.arrive.expect_tx.shared.b64 _, [%0], %1;"
                     :: "r"(bar_local + 8), "r"(2048u) : "memory");
    }
    float c_state = 0.0f;
    __syncthreads();
    CLUSTER_SYNC();   // peer barriers armed before any bulk copy

    // cluster-mapped peer addresses (hoisted)
    u32 part_peer_c, bar_peer_c;
    asm("mapa.shared::cluster.u32 %0, %1, %2;" : "=r"(part_peer_c) : "r"(part_local), "r"((u32)(rank^1)));
    asm("mapa.shared::cluster.u32 %0, %1, %2;" : "=r"(bar_peer_c)  : "r"(bar_local),  "r"((u32)(rank^1)));
    u32 myrow = (u32)rank * 2048u;     // my source row offset within a parity buf

    const float* preB = g_pre + d*512;
    float* hcatB = g_hcat + d*HID;

    // prefetch pre-activations for step 0
    float pn0 = 0.f, pn1 = 0.f, pn2 = 0.f, pn3 = 0.f;
    if (g < HID) {
        int t0 = d ? (T_FRAMES - 1) : 0;
        const float* pr = preB + (size_t)(t0*BATCH + b)*1024 + g;
        pn0 = pr[0]; pn1 = pr[128]; pn2 = pr[256]; pn3 = pr[384];
    }

    for (int s = 0; s < T_FRAMES; s++) {
        int t = d ? (T_FRAMES - 1 - s) : s;
        int row = t*BATCH + b;
        u32 par = (u32)(s & 1);
        u32 ph  = (u32)((s >> 1) & 1);

        float p0 = pn0, p1 = pn1, p2 = pn2, p3 = pn3;
        // prefetch NEXT step's pre-activations — a full step of latency overlap
        if (g < HID && s + 1 < T_FRAMES) {
            int tn = d ? (T_FRAMES - 2 - s) : (s + 1);
            const float* pr = preB + (size_t)(tn*BATCH + b)*1024 + g;
            pn0 = pr[0]; pn1 = pr[128]; pn2 = pr[256]; pn3 = pr[384];
        }

        // partial dot over this rank's k-half: 32 packed FFMA2
        ull a0 = 0ULL, a1 = 0ULL, a2 = 0ULL, a3 = 0ULL;
        const ulonglong2* hh = (const ulonglong2*)(h2_sh + rank*32);
        #pragma unroll
        for (int j = 0; j < 8; j++) {
            ulonglong2 hA = hh[2*j], hB = hh[2*j+1];
            a0 = ffma2(w2[4*j+0], hA.x, a0);
            a1 = ffma2(w2[4*j+1], hA.y, a1);
            a2 = ffma2(w2[4*j+2], hB.x, a2);
            a3 = ffma2(w2[4*j+3], hB.y, a3);
        }
        float2 f0v = u2f2(a0), f1v = u2f2(a1), f2v = u2f2(a2), f3v = u2f2(a3);
        float partial = ((f0v.x + f0v.y) + (f1v.x + f1v.y))
                      + ((f2v.x + f2v.y) + (f3v.x + f3v.y));

        partbuf[par][rank][g] = partial;      // local STS only
        __syncthreads();                      // partials visible block-wide

        if (g == 0) {
            // order generic STS before async-proxy read, then one bulk copy
            asm volatile("fence.proxy.async.shared::cta;" ::: "memory");
            u32 src = part_local + par*4096u + myrow;
            u32 dst = part_peer_c + par*4096u + myrow;
            asm volatile("cp.async.bulk.shared::cluster.shared::cta.mbarrier::complete_tx::bytes "
                         "[%0], [%1], %2, [%3];"
                         :: "r"(dst), "r"(src), "r"(2048u), "r"(bar_peer_c + 8u*par) : "memory");
        }

        // wait for the peer's 2048B of this step
        asm volatile("{\n\t"
                     ".reg .pred P;\n"
                     "LW%=:\n\t"
                     "mbarrier.try_wait.parity.acquire.cluster.shared::cta.b64 P, [%0], %1, 0x989680;\n\t"
                     "@!P bra LW%=;\n\t"
                     "}" :: "r"(bar_local + 8u*par), "r"(ph) : "memory");

        // re-arm this parity barrier for step s+2 (provably before peer can send it)
        if (g == 0 && s + 2 < T_FRAMES) {
            asm volatile("mbarrier.arrive.expect_tx.shared.b64 _, [%0], %1;"
                         :: "r"(bar_local + 8u*par), "r"(2048u) : "memory");
        }

        if (g < HID) {
            const float* lo = partbuf[par][0];   // k-low half (rank 0)
            const float* hi = partbuf[par][1];   // k-high half (rank 1)
            float zi = (lo[g]     + hi[g])     + p0;
            float zf = (lo[g+128] + hi[g+128]) + p1;
            float zg = (lo[g+256] + hi[g+256]) + p2;
            float zo = (lo[g+384] + hi[g+384]) + p3;
            c_state = fsigm(zf)*c_state + fsigm(zi)*ftanh(zg);
            float h = fsigm(zo)*ftanh(c_state);
            ((float*)h2_sh)[g] = h;
            if (rank == 0) hcatB[(size_t)row*256 + g] = h;
        }
        __syncthreads();   // h2_sh ready for next step's dot
    }
    CLUSTER_SYNC();        // no CTA exits with peer traffic in flight
}

// ----------------------- LayerNorm + output GEMM --------------------------
__global__ __launch_bounds__(256) void final_kernel(const float* __restrict__ ln_g,
                                                    const float* __restrict__ ln_b,
                                                    const float* __restrict__ out_b,
                                                    float* __restrict__ out)
{
    __shared__ float sh[16*256];
    __shared__ float s_sum[256], s_sq[256];
    __shared__ float s_mu[16], s_rstd[16];

    int t = blockIdx.x, tid = threadIdx.x;
    for (int i = tid; i < 4096; i += 256) sh[i] = g_hcat[t*4096 + i];
    __syncthreads();

    {
        int row = tid >> 4, seg = tid & 15;
        float sm = 0.f, sq = 0.f;
        const float* p = sh + row*256 + seg*16;
        #pragma unroll
        for (int u = 0; u < 16; u++) { float v = p[u]; sm += v; sq += v*v; }
        s_sum[tid] = sm; s_sq[tid] = sq;
    }
    __syncthreads();
    if (tid < 16) {
        float sm = 0.f, sq = 0.f;
        #pragma unroll
        for (int u = 0; u < 16; u++) { sm += s_sum[tid*16 + u]; sq += s_sq[tid*16 + u]; }
        float mu = sm * (1.0f/256.0f);
        float var = sq * (1.0f/256.0f) - mu*mu;
        s_mu[tid] = mu;
        s_rstd[tid] = rsqrtf(var + 1e-5f);
    }
    __syncthreads();
    for (int i = tid; i < 4096; i += 256) {
        int r = i >> 8, k = i & 255;
        sh[i] = (sh[i] - s_mu[r]) * s_rstd[r] * ln_g[k] + ln_b[k];
    }
    __syncthreads();

    int col = tid & 63, rg = tid >> 6;
    float acc[4];
    float bb = out_b[col];
    #pragma unroll
    for (int r = 0; r < 4; r++) acc[r] = bb;
    for (int k = 0; k < 256; k++) {
        float w = g_owT[k*64 + col];
        #pragma unroll
        for (int r = 0; r < 4; r++) acc[r] += sh[(rg*4 + r)*256 + k] * w;
    }
    #pragma unroll
    for (int r = 0; r < 4; r++) {
        int b = rg*4 + r;
        out[(b*T_FRAMES + t)*DOUTN + col] = acc[r];
    }
}

// ------------------------------ launcher ----------------------------------
extern "C" void kernel_launch(void* const* d_in, const int* in_sizes, int n_in,
                              void* d_out, int out_size)
{
    const float* x     = (const float*)d_in[0];
    const float* f0    = (const float*)d_in[1];
    const float* wihf  = (const float*)d_in[2];
    const float* whhf  = (const float*)d_in[3];
    const float* bf    = (const float*)d_in[4];
    const float* wihb  = (const float*)d_in[5];
    const float* whhb  = (const float*)d_in[6];
    const float* bb    = (const float*)d_in[7];
    const float* lng   = (const float*)d_in[8];
    const float* lnb   = (const float*)d_in[9];
    const float* outw  = (const float*)d_in[10];
    const float* outb  = (const float*)d_in[11];
    float* out = (float*)d_out;

    prep_kernel<<<256, 256>>>(wihf, whhf, bf, wihb, whhb, bb, outw);
    stft_kernel<<<dim3(T_FRAMES, BATCH), 256>>>(x, f0);
    pre_gemm_kernel<<<dim3(T_FRAMES, 2), 256>>>();
    lstm_kernel<<<64, 512>>>();
    final_kernel<<<T_FRAMES, 256>>>(lng, lnb, outb, out);
}